// round 9
// baseline (speedup 1.0000x reference)
#include <cuda_runtime.h>
#include <cstdint>
#include <math.h>

// Problem constants
#define B       2
#define S       2048
#define D       1024
#define HEADS   16
#define DH      64
#define INNER   1024
#define D3      3072
#define ROWS    4096
#define LN_EPS  1e-5f
// 0.125 * log2(e): folded into Q so softmax runs in base 2
#define QSCALE_LOG2E 0.18033688011112042f

// Scratch: xn | qkv | ctx | w_qkv rounded | w_out rounded
__device__ float g_scratch[(size_t)ROWS * D + (size_t)ROWS * D3 + (size_t)ROWS * D
                           + (size_t)D * D3 + (size_t)D * D];

// ---------------------------------------------------------------------------
// Helpers
// ---------------------------------------------------------------------------
__device__ __forceinline__ uint32_t smem_u32(const void* p) {
    uint32_t a;
    asm("{ .reg .u64 t; cvta.to.shared.u64 t, %1; cvt.u32.u64 %0, t; }" : "=r"(a) : "l"(p));
    return a;
}
__device__ __forceinline__ float tf32r(float x) {
    uint32_t o;
    asm("cvt.rna.tf32.f32 %0, %1;" : "=r"(o) : "f"(x));
    return __uint_as_float(o);
}
__device__ __forceinline__ float ex2f(float x) {
    float r;
    asm("ex2.approx.ftz.f32 %0, %1;" : "=f"(r) : "f"(x));
    return r;
}

#define CP_ASYNC16(dst, src) \
    asm volatile("cp.async.cg.shared.global [%0], [%1], 16;" :: "r"(dst), "l"(src))
#define CP_COMMIT()  asm volatile("cp.async.commit_group;" ::: "memory")
#define CP_WAIT1()   asm volatile("cp.async.wait_group 1;" ::: "memory")
#define CP_WAIT0()   asm volatile("cp.async.wait_group 0;" ::: "memory")

__device__ __forceinline__ void mma_tf32(
    float& d0, float& d1, float& d2, float& d3,
    uint32_t a0, uint32_t a1, uint32_t a2, uint32_t a3,
    uint32_t b0, uint32_t b1)
{
    asm volatile(
        "mma.sync.aligned.m16n8k8.row.col.f32.tf32.tf32.f32 "
        "{%0,%1,%2,%3}, {%4,%5,%6,%7}, {%8,%9}, {%0,%1,%2,%3};"
        : "+f"(d0), "+f"(d1), "+f"(d2), "+f"(d3)
        : "r"(a0), "r"(a1), "r"(a2), "r"(a3), "r"(b0), "r"(b1));
}
#define U(x) __float_as_uint(x)

// ---------------------------------------------------------------------------
// LayerNorm (output rounded to tf32)
// ---------------------------------------------------------------------------
__global__ __launch_bounds__(256) void ln_kernel(
    const float* __restrict__ x, const float* __restrict__ gamma,
    const float* __restrict__ beta, float* __restrict__ y)
{
    const int row = blockIdx.x;
    const int t = threadIdx.x;
    const float4* xp = (const float4*)(x + (size_t)row * D);
    float4 v = xp[t];
    float s  = v.x + v.y + v.z + v.w;
    float ss = v.x * v.x + v.y * v.y + v.z * v.z + v.w * v.w;
    #pragma unroll
    for (int off = 16; off > 0; off >>= 1) {
        s  += __shfl_down_sync(0xffffffffu, s,  off);
        ss += __shfl_down_sync(0xffffffffu, ss, off);
    }
    __shared__ float sh_s[8], sh_ss[8];
    const int w = t >> 5, lane = t & 31;
    if (lane == 0) { sh_s[w] = s; sh_ss[w] = ss; }
    __syncthreads();
    __shared__ float mu_sh, rstd_sh;
    if (t == 0) {
        float S0 = 0.f, SS0 = 0.f;
        #pragma unroll
        for (int i = 0; i < 8; i++) { S0 += sh_s[i]; SS0 += sh_ss[i]; }
        const float mu  = S0 * (1.0f / D);
        const float var = SS0 * (1.0f / D) - mu * mu;
        mu_sh = mu;
        rstd_sh = rsqrtf(var + LN_EPS);
    }
    __syncthreads();
    const float mu = mu_sh, rstd = rstd_sh;
    float4 g  = ((const float4*)gamma)[t];
    float4 bb = ((const float4*)beta)[t];
    float4 o;
    o.x = tf32r((v.x - mu) * rstd * g.x + bb.x);
    o.y = tf32r((v.y - mu) * rstd * g.y + bb.y);
    o.z = tf32r((v.z - mu) * rstd * g.z + bb.z);
    o.w = tf32r((v.w - mu) * rstd * g.w + bb.w);
    ((float4*)(y + (size_t)row * D))[t] = o;
}

// ---------------------------------------------------------------------------
// Round a weight array to tf32 (rna)
// ---------------------------------------------------------------------------
__global__ __launch_bounds__(256) void round_kernel(
    const float* __restrict__ src, float* __restrict__ dst, int n4)
{
    int i = blockIdx.x * 256 + threadIdx.x;
    if (i < n4) {
        float4 v = ((const float4*)src)[i];
        v.x = tf32r(v.x); v.y = tf32r(v.y); v.z = tf32r(v.z); v.w = tf32r(v.w);
        ((float4*)dst)[i] = v;
    }
}

// ---------------------------------------------------------------------------
// TF32 mma.sync GEMM: C[M,N] = A[M,K=1024] @ W[K,N] (+bias)
// 128x128 tile, BK=32, 256 threads (8 warps, warp-tile 32x64), cp.async x2.
// (R3-exact version: fastest measured, 197.7us on QKV)
// ---------------------------------------------------------------------------
#define GA_P 36
#define GB_P 136
#define GA_ST (128 * GA_P)
#define GB_ST (32 * GB_P)
#define GEMM_SMEM ((2 * GA_ST + 2 * GB_ST) * 4)   // 71680 B

__global__ __launch_bounds__(256, 2) void gemm_kernel(
    const float* __restrict__ A, const float* __restrict__ W,
    const float* __restrict__ bias, float* __restrict__ C,
    int N, int round_out)
{
    extern __shared__ float sm[];
    const int tid = threadIdx.x;
    const int wid = tid >> 5, lane = tid & 31;
    const int gID = lane >> 2, tg = lane & 3;
    const int bm = blockIdx.y * 128, bn = blockIdx.x * 128;
    const int wm = (wid & 3) * 32, wn = (wid >> 2) * 64;

    float* Asm[2] = { sm, sm + GA_ST };
    float* Bsm[2] = { sm + 2 * GA_ST, sm + 2 * GA_ST + GB_ST };
    const uint32_t aB[2] = { smem_u32(Asm[0]), smem_u32(Asm[1]) };
    const uint32_t bB[2] = { smem_u32(Bsm[0]), smem_u32(Bsm[1]) };

    float acc[2][8][4];
    #pragma unroll
    for (int im = 0; im < 2; im++)
        #pragma unroll
        for (int n = 0; n < 8; n++)
            #pragma unroll
            for (int j = 0; j < 4; j++) acc[im][n][j] = 0.f;

    // prologue: chunks 0,1
    #pragma unroll
    for (int pi = 0; pi < 2; pi++) {
        const int k0 = pi * 32;
        #pragma unroll
        for (int j = 0; j < 4; j++) {
            const int idx = tid + j * 256;
            const int r = idx >> 3, c = idx & 7;
            CP_ASYNC16(aB[pi] + (uint32_t)(r * GA_P + c * 4) * 4u,
                       A + (size_t)(bm + r) * D + k0 + c * 4);
        }
        #pragma unroll
        for (int j = 0; j < 4; j++) {
            const int idx = tid + j * 256;
            const int r = idx >> 5, c = idx & 31;
            CP_ASYNC16(bB[pi] + (uint32_t)(r * GB_P + c * 4) * 4u,
                       W + (size_t)(k0 + r) * N + bn + c * 4);
        }
        CP_COMMIT();
    }

    for (int i = 0; i < 32; i++) {
        const int s = i & 1;
        if (i < 31) { CP_WAIT1(); } else { CP_WAIT0(); }
        __syncthreads();
        const float* as = Asm[s];
        const float* bs = Bsm[s];
        #pragma unroll
        for (int ks = 0; ks < 4; ks++) {
            const int k = ks * 8;
            uint32_t af[2][4];
            #pragma unroll
            for (int im = 0; im < 2; im++) {
                const float* p = as + (wm + im * 16 + gID) * GA_P + k + tg;
                af[im][0] = U(p[0]);
                af[im][1] = U(p[8 * GA_P]);
                af[im][2] = U(p[4]);
                af[im][3] = U(p[8 * GA_P + 4]);
            }
            #pragma unroll
            for (int n = 0; n < 8; n++) {
                const float* p = bs + (k + tg) * GB_P + wn + n * 8 + gID;
                const uint32_t b0 = U(p[0]);
                const uint32_t b1 = U(p[4 * GB_P]);
                #pragma unroll
                for (int im = 0; im < 2; im++)
                    mma_tf32(acc[im][n][0], acc[im][n][1], acc[im][n][2], acc[im][n][3],
                             af[im][0], af[im][1], af[im][2], af[im][3], b0, b1);
            }
        }
        __syncthreads();
        if (i + 2 < 32) {
            const int k0 = (i + 2) * 32;
            #pragma unroll
            for (int j = 0; j < 4; j++) {
                const int idx = tid + j * 256;
                const int r = idx >> 3, c = idx & 7;
                CP_ASYNC16(aB[s] + (uint32_t)(r * GA_P + c * 4) * 4u,
                           A + (size_t)(bm + r) * D + k0 + c * 4);
            }
            #pragma unroll
            for (int j = 0; j < 4; j++) {
                const int idx = tid + j * 256;
                const int r = idx >> 5, c = idx & 31;
                CP_ASYNC16(bB[s] + (uint32_t)(r * GB_P + c * 4) * 4u,
                           W + (size_t)(k0 + r) * N + bn + c * 4);
            }
            CP_COMMIT();
        }
    }

    // epilogue
    #pragma unroll
    for (int im = 0; im < 2; im++) {
        const int r0 = bm + wm + im * 16 + gID;
        #pragma unroll
        for (int n = 0; n < 8; n++) {
            const int col = bn + wn + n * 8 + 2 * tg;
            float v0 = acc[im][n][0], v1 = acc[im][n][1];
            float v2 = acc[im][n][2], v3 = acc[im][n][3];
            if (bias) {
                const float b0 = bias[col], b1 = bias[col + 1];
                v0 += b0; v1 += b1; v2 += b0; v3 += b1;
            }
            if (round_out) {
                v0 = tf32r(v0); v1 = tf32r(v1); v2 = tf32r(v2); v3 = tf32r(v3);
            }
            *(float2*)&C[(size_t)r0 * N + col]       = make_float2(v0, v1);
            *(float2*)&C[(size_t)(r0 + 8) * N + col] = make_float2(v2, v3);
        }
    }
}

// ---------------------------------------------------------------------------
// TF32 mma.sync flash attention.
//  - register-resident P (R5 key-relabel: S acc IS the PV A-fragment)
//  - d-permuted K frags (LDS.128, pitch 80)
//  - base-2 softmax (log2e folded into Q, raw ex2.approx)
//  - NEW: PV n-axis relabeled col(n_iter,slot)=slot*8+n_iter so V B-operand
//    reads are 4x LDS.128 per kf (was 16x LDS.32). V stored with a 1-bit
//    XOR swizzle on the float4 slot (f ^ ((row>>1)&1)) -> conflict-free.
//    Output cols per thread become [16tg, 16tg+16) rows gID, gID+8.
// Block: 256 threads / 8 warps, 128 queries (16/warp), 64-key tiles, 2-stage.
// grid (S/128, HEADS, B)
// ---------------------------------------------------------------------------
#define KP 80
#define VP 68
#define K_ST (64 * KP)
#define V_ST (64 * VP)
#define ATTN_SMEM ((2 * K_ST + 2 * V_ST) * 4)   // 75776 B

__global__ __launch_bounds__(256, 2) void attn_kernel(
    const float* __restrict__ qkv, float* __restrict__ ctx)
{
    extern __shared__ float sm[];
    float* Ksm[2] = { sm, sm + K_ST };
    float* Vsm[2] = { sm + 2 * K_ST, sm + 2 * K_ST + V_ST };
    const uint32_t kB[2] = { smem_u32(Ksm[0]), smem_u32(Ksm[1]) };
    const uint32_t vB[2] = { smem_u32(Vsm[0]), smem_u32(Vsm[1]) };

    const int tid = threadIdx.x;
    const int wid = tid >> 5, lane = tid & 31;
    const int gID = lane >> 2, tg = lane & 3;
    const int h = blockIdx.y, bb = blockIdx.z;
    const int qbase = blockIdx.x * 128 + wid * 16;

    const float* qp = qkv + (size_t)(bb * S + qbase) * D3 + h * DH;
    const float* kbase = qkv + (size_t)bb * S * D3 + INNER + h * DH;
    const float* vbase = kbase + INNER;

    // Q fragments: d-permuted float4 loads; fold 0.125*log2e, rna-round to tf32
    float4 qf[4][2];
    #pragma unroll
    for (int kg = 0; kg < 4; kg++) {
        float4 v0 = *(const float4*)(qp + (size_t)gID * D3 + kg * 16 + 4 * tg);
        float4 v1 = *(const float4*)(qp + (size_t)(gID + 8) * D3 + kg * 16 + 4 * tg);
        v0.x = tf32r(v0.x * QSCALE_LOG2E); v0.y = tf32r(v0.y * QSCALE_LOG2E);
        v0.z = tf32r(v0.z * QSCALE_LOG2E); v0.w = tf32r(v0.w * QSCALE_LOG2E);
        v1.x = tf32r(v1.x * QSCALE_LOG2E); v1.y = tf32r(v1.y * QSCALE_LOG2E);
        v1.z = tf32r(v1.z * QSCALE_LOG2E); v1.w = tf32r(v1.w * QSCALE_LOG2E);
        qf[kg][0] = v0; qf[kg][1] = v1;
    }

    float o[8][4];
    #pragma unroll
    for (int n = 0; n < 8; n++)
        #pragma unroll
        for (int j = 0; j < 4; j++) o[n][j] = 0.f;
    float m0 = -1e30f, m1 = -1e30f, l0 = 0.f, l1 = 0.f;

    // prologue: tiles 0,1  (V stored with XOR-swizzled float4 slot)
    #pragma unroll
    for (int pi = 0; pi < 2; pi++) {
        const int r0 = pi * 64;
        #pragma unroll
        for (int j = 0; j < 4; j++) {
            const int idx = tid + j * 256;
            const int r = idx >> 4, f4 = idx & 15;
            CP_ASYNC16(kB[pi] + (uint32_t)(r * KP + f4 * 4) * 4u,
                       kbase + (size_t)(r0 + r) * D3 + f4 * 4);
            const int f4v = f4 ^ ((r >> 1) & 1);
            CP_ASYNC16(vB[pi] + (uint32_t)(r * VP + f4v * 4) * 4u,
                       vbase + (size_t)(r0 + r) * D3 + f4 * 4);
        }
        CP_COMMIT();
    }

    for (int i = 0; i < 32; i++) {
        const int s = i & 1;
        if (i < 31) { CP_WAIT1(); } else { CP_WAIT0(); }
        __syncthreads();

        // ---- S = Q @ K^T  (d-permuted fragments, base-2 scaled) ----
        float sa[8][4];
        #pragma unroll
        for (int n = 0; n < 8; n++)
            #pragma unroll
            for (int j = 0; j < 4; j++) sa[n][j] = 0.f;
        const float* ks = Ksm[s];
        #pragma unroll
        for (int kg = 0; kg < 4; kg++) {
            #pragma unroll
            for (int n = 0; n < 8; n++) {
                const float4 kv = *(const float4*)(ks + (n * 8 + gID) * KP + kg * 16 + 4 * tg);
                mma_tf32(sa[n][0], sa[n][1], sa[n][2], sa[n][3],
                         U(qf[kg][0].x), U(qf[kg][1].x), U(qf[kg][0].y), U(qf[kg][1].y),
                         U(kv.x), U(kv.y));
                mma_tf32(sa[n][0], sa[n][1], sa[n][2], sa[n][3],
                         U(qf[kg][0].z), U(qf[kg][1].z), U(qf[kg][0].w), U(qf[kg][1].w),
                         U(kv.z), U(kv.w));
            }
        }

        // ---- online softmax in base 2 (P in registers, tf32-rounded) ----
        float rmax0 = sa[0][0], rmax1 = sa[0][2];
        #pragma unroll
        for (int n = 0; n < 8; n++) {
            rmax0 = fmaxf(rmax0, fmaxf(sa[n][0], sa[n][1]));
            rmax1 = fmaxf(rmax1, fmaxf(sa[n][2], sa[n][3]));
        }
        rmax0 = fmaxf(rmax0, __shfl_xor_sync(0xffffffffu, rmax0, 1));
        rmax0 = fmaxf(rmax0, __shfl_xor_sync(0xffffffffu, rmax0, 2));
        rmax1 = fmaxf(rmax1, __shfl_xor_sync(0xffffffffu, rmax1, 1));
        rmax1 = fmaxf(rmax1, __shfl_xor_sync(0xffffffffu, rmax1, 2));
        const float nm0 = fmaxf(m0, rmax0), nm1 = fmaxf(m1, rmax1);
        const float c0 = ex2f(m0 - nm0), c1 = ex2f(m1 - nm1);
        m0 = nm0; m1 = nm1;
        float s0 = 0.f, s1 = 0.f;
        #pragma unroll
        for (int n = 0; n < 8; n++) {
            const float p0 = ex2f(sa[n][0] - m0);
            const float p1 = ex2f(sa[n][1] - m0);
            const float p2 = ex2f(sa[n][2] - m1);
            const float p3 = ex2f(sa[n][3] - m1);
            s0 += p0 + p1; s1 += p2 + p3;
            sa[n][0] = tf32r(p0); sa[n][1] = tf32r(p1);
            sa[n][2] = tf32r(p2); sa[n][3] = tf32r(p3);
            o[n][0] *= c0; o[n][1] *= c0; o[n][2] *= c1; o[n][3] *= c1;
        }
        s0 += __shfl_xor_sync(0xffffffffu, s0, 1);
        s0 += __shfl_xor_sync(0xffffffffu, s0, 2);
        s1 += __shfl_xor_sync(0xffffffffu, s1, 1);
        s1 += __shfl_xor_sync(0xffffffffu, s1, 2);
        l0 = l0 * c0 + s0;
        l1 = l1 * c1 + s1;

        // ---- O += P @ V  (key-relabel A; n-axis relabeled -> LDS.128 V) ----
        // col(n_iter, slot) = slot*8 + n_iter; this thread's B column = gID*8 + n_iter.
        // Physical f4 slot = logical ^ (tg&1)  (matches store swizzle, since
        // rows are 2tg+8kf and 2tg+1+8kf -> (row>>1)&1 == tg&1).
        const float* vs = Vsm[s];
        const int sw = tg & 1;
        const int fa = (2 * gID) ^ sw, fb = (2 * gID + 1) ^ sw;
        #pragma unroll
        for (int kf = 0; kf < 8; kf++) {
            const uint32_t a0 = U(sa[kf][0]);
            const uint32_t a1 = U(sa[kf][2]);
            const uint32_t a2 = U(sa[kf][1]);
            const uint32_t a3 = U(sa[kf][3]);
            const float* r0p = vs + (kf * 8 + 2 * tg) * VP;
            const float* r1p = r0p + VP;
            const float4 v0a = *(const float4*)(r0p + fa * 4);
            const float4 v0b = *(const float4*)(r0p + fb * 4);
            const float4 v1a = *(const float4*)(r1p + fa * 4);
            const float4 v1b = *(const float4*)(r1p + fb * 4);
            mma_tf32(o[0][0], o[0][1], o[0][2], o[0][3], a0, a1, a2, a3, U(v0a.x), U(v1a.x));
            mma_tf32(o[1][0], o[1][1], o[1][2], o[1][3], a0, a1, a2, a3, U(v0a.y), U(v1a.y));
            mma_tf32(o[2][0], o[2][1], o[2][2], o[2][3], a0, a1, a2, a3, U(v0a.z), U(v1a.z));
            mma_tf32(o[3][0], o[3][1], o[3][2], o[3][3], a0, a1, a2, a3, U(v0a.w), U(v1a.w));
            mma_tf32(o[4][0], o[4][1], o[4][2], o[4][3], a0, a1, a2, a3, U(v0b.x), U(v1b.x));
            mma_tf32(o[5][0], o[5][1], o[5][2], o[5][3], a0, a1, a2, a3, U(v0b.y), U(v1b.y));
            mma_tf32(o[6][0], o[6][1], o[6][2], o[6][3], a0, a1, a2, a3, U(v0b.z), U(v1b.z));
            mma_tf32(o[7][0], o[7][1], o[7][2], o[7][3], a0, a1, a2, a3, U(v0b.w), U(v1b.w));
        }
        __syncthreads();

        if (i + 2 < 32) {
            const int r0 = (i + 2) * 64;
            #pragma unroll
            for (int j = 0; j < 4; j++) {
                const int idx = tid + j * 256;
                const int r = idx >> 4, f4 = idx & 15;
                CP_ASYNC16(kB[s] + (uint32_t)(r * KP + f4 * 4) * 4u,
                           kbase + (size_t)(r0 + r) * D3 + f4 * 4);
                const int f4v = f4 ^ ((r >> 1) & 1);
                CP_ASYNC16(vB[s] + (uint32_t)(r * VP + f4v * 4) * 4u,
                           vbase + (size_t)(r0 + r) * D3 + f4 * 4);
            }
            CP_COMMIT();
        }
    }

    // epilogue. o[n][0] = O[gID][16tg+n], o[n][1] = O[gID][16tg+8+n],
    //           o[n][2], o[n][3] = same cols, row gID+8.  (rounded for out-proj)
    const float inv0 = 1.f / l0, inv1 = 1.f / l1;
    const size_t grow = (size_t)(bb * S + qbase + gID);
    float* out0 = &ctx[grow * INNER + h * DH + 16 * tg];
    float* out1 = &ctx[(grow + 8) * INNER + h * DH + 16 * tg];
    #pragma unroll
    for (int half = 0; half < 2; half++) {   // cols +0..7 (j=0), +8..15 (j=1)
        float4 s0v, s1v, s2v, s3v;
        s0v.x = tf32r(o[0][half] * inv0); s0v.y = tf32r(o[1][half] * inv0);
        s0v.z = tf32r(o[2][half] * inv0); s0v.w = tf32r(o[3][half] * inv0);
        s1v.x = tf32r(o[4][half] * inv0); s1v.y = tf32r(o[5][half] * inv0);
        s1v.z = tf32r(o[6][half] * inv0); s1v.w = tf32r(o[7][half] * inv0);
        s2v.x = tf32r(o[0][half + 2] * inv1); s2v.y = tf32r(o[1][half + 2] * inv1);
        s2v.z = tf32r(o[2][half + 2] * inv1); s2v.w = tf32r(o[3][half + 2] * inv1);
        s3v.x = tf32r(o[4][half + 2] * inv1); s3v.y = tf32r(o[5][half + 2] * inv1);
        s3v.z = tf32r(o[6][half + 2] * inv1); s3v.w = tf32r(o[7][half + 2] * inv1);
        *(float4*)(out0 + half * 8)     = s0v;
        *(float4*)(out0 + half * 8 + 4) = s1v;
        *(float4*)(out1 + half * 8)     = s2v;
        *(float4*)(out1 + half * 8 + 4) = s3v;
    }
}

// ---------------------------------------------------------------------------
extern "C" void kernel_launch(void* const* d_in, const int* in_sizes, int n_in,
                              void* d_out, int out_size)
{
    const float* x        = (const float*)d_in[0];
    const float* ln_gamma = (const float*)d_in[1];
    const float* ln_beta  = (const float*)d_in[2];
    const float* w_qkv    = (const float*)d_in[3];
    const float* w_out    = (const float*)d_in[4];
    const float* b_out    = (const float*)d_in[5];
    float* out = (float*)d_out;

    void* sp = nullptr;
    cudaGetSymbolAddress(&sp, g_scratch);
    float* xn   = (float*)sp;
    float* qkv  = xn + (size_t)ROWS * D;
    float* ctx  = qkv + (size_t)ROWS * D3;
    float* wq_r = ctx + (size_t)ROWS * D;
    float* wo_r = wq_r + (size_t)D * D3;

    cudaFuncSetAttribute(gemm_kernel, cudaFuncAttributeMaxDynamicSharedMemorySize, GEMM_SMEM);
    cudaFuncSetAttribute(attn_kernel, cudaFuncAttributeMaxDynamicSharedMemorySize, ATTN_SMEM);

    // round weights to tf32 (unbiased rna)
    round_kernel<<<(D * D3 / 4 + 255) / 256, 256>>>(w_qkv, wq_r, D * D3 / 4);
    round_kernel<<<(D * D / 4 + 255) / 256, 256>>>(w_out, wo_r, D * D / 4);

    // 1. LayerNorm (tf32-rounded output)
    ln_kernel<<<ROWS, 256>>>(x, ln_gamma, ln_beta, xn);

    // 2. QKV projection (tensor cores, tf32-rounded output)
    gemm_kernel<<<dim3(D3 / 128, ROWS / 128), 256, GEMM_SMEM>>>(
        xn, wq_r, nullptr, qkv, D3, 1);

    // 3. Flash attention (tensor cores, register P, all-LDS.128 operands)
    attn_kernel<<<dim3(S / 128, HEADS, B), 256, ATTN_SMEM>>>(qkv, ctx);

    // 4. Output projection + bias (tensor cores, full fp32 out)
    gemm_kernel<<<dim3(D / 128, ROWS / 128), 256, GEMM_SMEM>>>(
        ctx, wo_r, b_out, out, D, 0);
}

// round 10
// speedup vs baseline: 1.3829x; 1.3829x over previous
#include <cuda_runtime.h>
#include <cuda_fp16.h>
#include <cstdint>
#include <math.h>

// Problem constants
#define B       2
#define S       2048
#define D       1024
#define HEADS   16
#define DH      64
#define INNER   1024
#define D3      3072
#define ROWS    4096
#define LN_EPS  1e-5f
// 0.125 * log2(e): folded into Q so softmax runs in base 2
#define QSCALE_LOG2E 0.18033688011112042f

// Scratch: xn(half) | qkv(f32) | ctx(half) | w_qkv packed | w_out packed
__device__ float g_scratch[(size_t)ROWS * D + (size_t)ROWS * D3 + (size_t)ROWS * D
                           + (size_t)D * D3 + (size_t)D * D];

// ---------------------------------------------------------------------------
// Helpers
// ---------------------------------------------------------------------------
__device__ __forceinline__ uint32_t smem_u32(const void* p) {
    uint32_t a;
    asm("{ .reg .u64 t; cvta.to.shared.u64 t, %1; cvt.u32.u64 %0, t; }" : "=r"(a) : "l"(p));
    return a;
}
__device__ __forceinline__ float tf32r(float x) {
    uint32_t o;
    asm("cvt.rna.tf32.f32 %0, %1;" : "=r"(o) : "f"(x));
    return __uint_as_float(o);
}
__device__ __forceinline__ float ex2f(float x) {
    float r;
    asm("ex2.approx.ftz.f32 %0, %1;" : "=f"(r) : "f"(x));
    return r;
}
__device__ __forceinline__ uint32_t packh2(float lo, float hi) {
    __half2 h = __halves2half2(__float2half_rn(lo), __float2half_rn(hi));
    return *(uint32_t*)&h;
}

#define CP_ASYNC16(dst, src) \
    asm volatile("cp.async.cg.shared.global [%0], [%1], 16;" :: "r"(dst), "l"(src))
#define CP_COMMIT()  asm volatile("cp.async.commit_group;" ::: "memory")
#define CP_WAIT1()   asm volatile("cp.async.wait_group 1;" ::: "memory")
#define CP_WAIT0()   asm volatile("cp.async.wait_group 0;" ::: "memory")

__device__ __forceinline__ void mma_tf32(
    float& d0, float& d1, float& d2, float& d3,
    uint32_t a0, uint32_t a1, uint32_t a2, uint32_t a3,
    uint32_t b0, uint32_t b1)
{
    asm volatile(
        "mma.sync.aligned.m16n8k8.row.col.f32.tf32.tf32.f32 "
        "{%0,%1,%2,%3}, {%4,%5,%6,%7}, {%8,%9}, {%0,%1,%2,%3};"
        : "+f"(d0), "+f"(d1), "+f"(d2), "+f"(d3)
        : "r"(a0), "r"(a1), "r"(a2), "r"(a3), "r"(b0), "r"(b1));
}
__device__ __forceinline__ void mma_f16(
    float& d0, float& d1, float& d2, float& d3,
    uint32_t a0, uint32_t a1, uint32_t a2, uint32_t a3,
    uint32_t b0, uint32_t b1)
{
    asm volatile(
        "mma.sync.aligned.m16n8k16.row.col.f32.f16.f16.f32 "
        "{%0,%1,%2,%3}, {%4,%5,%6,%7}, {%8,%9}, {%0,%1,%2,%3};"
        : "+f"(d0), "+f"(d1), "+f"(d2), "+f"(d3)
        : "r"(a0), "r"(a1), "r"(a2), "r"(a3), "r"(b0), "r"(b1));
}
#define U(x) __float_as_uint(x)

// ---------------------------------------------------------------------------
// LayerNorm (output written as fp16, rn)
// ---------------------------------------------------------------------------
__global__ __launch_bounds__(256) void ln_kernel(
    const float* __restrict__ x, const float* __restrict__ gamma,
    const float* __restrict__ beta, uint32_t* __restrict__ y)
{
    const int row = blockIdx.x;
    const int t = threadIdx.x;
    const float4* xp = (const float4*)(x + (size_t)row * D);
    float4 v = xp[t];
    float s  = v.x + v.y + v.z + v.w;
    float ss = v.x * v.x + v.y * v.y + v.z * v.z + v.w * v.w;
    #pragma unroll
    for (int off = 16; off > 0; off >>= 1) {
        s  += __shfl_down_sync(0xffffffffu, s,  off);
        ss += __shfl_down_sync(0xffffffffu, ss, off);
    }
    __shared__ float sh_s[8], sh_ss[8];
    const int w = t >> 5, lane = t & 31;
    if (lane == 0) { sh_s[w] = s; sh_ss[w] = ss; }
    __syncthreads();
    __shared__ float mu_sh, rstd_sh;
    if (t == 0) {
        float S0 = 0.f, SS0 = 0.f;
        #pragma unroll
        for (int i = 0; i < 8; i++) { S0 += sh_s[i]; SS0 += sh_ss[i]; }
        const float mu  = S0 * (1.0f / D);
        const float var = SS0 * (1.0f / D) - mu * mu;
        mu_sh = mu;
        rstd_sh = rsqrtf(var + LN_EPS);
    }
    __syncthreads();
    const float mu = mu_sh, rstd = rstd_sh;
    float4 g  = ((const float4*)gamma)[t];
    float4 bb = ((const float4*)beta)[t];
    const float ox = (v.x - mu) * rstd * g.x + bb.x;
    const float oy = (v.y - mu) * rstd * g.y + bb.y;
    const float oz = (v.z - mu) * rstd * g.z + bb.z;
    const float ow = (v.w - mu) * rstd * g.w + bb.w;
    ((uint2*)(y + (size_t)row * (D / 2)))[t] = make_uint2(packh2(ox, oy), packh2(oz, ow));
}

// ---------------------------------------------------------------------------
// Pack weights: W[K=1024][N] f32 -> Wp[j=K/2][N] u32 where
// Wp[j][n] = half2(W[2j][n] lo, W[2j+1][n] hi)   (fp16 mma B-operand layout)
// ---------------------------------------------------------------------------
__global__ __launch_bounds__(256) void pack_w_kernel(
    const float* __restrict__ W, uint32_t* __restrict__ Wp, int N)
{
    const int n4 = N >> 2;
    const int idx = blockIdx.x * 256 + threadIdx.x;
    if (idx >= 512 * n4) return;
    const int j = idx / n4, c = idx - j * n4;
    const float4 r0 = *(const float4*)(W + (size_t)(2 * j) * N + c * 4);
    const float4 r1 = *(const float4*)(W + (size_t)(2 * j + 1) * N + c * 4);
    uint4 o;
    o.x = packh2(r0.x, r1.x); o.y = packh2(r0.y, r1.y);
    o.z = packh2(r0.z, r1.z); o.w = packh2(r0.w, r1.w);
    *(uint4*)(Wp + (size_t)j * N + c * 4) = o;
}

// ---------------------------------------------------------------------------
// FP16 mma.sync GEMM: C[M,N] = A[M,K=1024] @ W[K,N] (+bias), f32 accumulate.
// A: half [M][1024]; W: packed Wp[512][N].  128x128 tile, BK=32 (2x k16),
// 256 threads, 8 warps (warp-tile 32x64), cp.async double-buffered.
// Pitches: A 40 halves (banks 20g+tg bijective), B 136 u32 (8tg+g bijective).
// ---------------------------------------------------------------------------
#define HA_P 40
#define HB_P 136
#define HA_ST (128 * HA_P)          // halves per A stage (10240 B)
#define HB_ST (16 * HB_P)           // u32 per B stage    (8704 B)
#define GEMM_SMEM (2 * (HA_ST * 2 + HB_ST * 4))   // 37888 B

__global__ __launch_bounds__(256, 2) void gemm_h_kernel(
    const __half* __restrict__ A, const uint32_t* __restrict__ Wp,
    const float* __restrict__ bias, float* __restrict__ C,
    int N, int round_out)
{
    extern __shared__ char smc[];
    __half* Ah[2]    = { (__half*)smc, (__half*)smc + HA_ST };
    uint32_t* Bw[2]  = { (uint32_t*)(smc + 2 * HA_ST * 2),
                         (uint32_t*)(smc + 2 * HA_ST * 2) + HB_ST };
    const uint32_t aB[2] = { smem_u32(Ah[0]), smem_u32(Ah[1]) };
    const uint32_t bB[2] = { smem_u32(Bw[0]), smem_u32(Bw[1]) };

    const int tid = threadIdx.x;
    const int wid = tid >> 5, lane = tid & 31;
    const int gID = lane >> 2, tg = lane & 3;
    const int bm = blockIdx.y * 128, bn = blockIdx.x * 128;
    const int wm = (wid & 3) * 32, wn = (wid >> 2) * 64;

    float acc[2][8][4];
    #pragma unroll
    for (int im = 0; im < 2; im++)
        #pragma unroll
        for (int n = 0; n < 8; n++)
            #pragma unroll
            for (int j = 0; j < 4; j++) acc[im][n][j] = 0.f;

    // prologue: chunks 0,1
    #pragma unroll
    for (int pi = 0; pi < 2; pi++) {
        const int k0 = pi * 32;
        #pragma unroll
        for (int j = 0; j < 2; j++) {
            const int idx = tid + j * 256;              // 0..511
            const int r = idx >> 2, c = idx & 3;        // A: 128 rows x 4 chunks
            CP_ASYNC16(aB[pi] + (uint32_t)(r * HA_P + c * 8) * 2u,
                       A + (size_t)(bm + r) * D + k0 + c * 8);
        }
        #pragma unroll
        for (int j = 0; j < 2; j++) {
            const int idx = tid + j * 256;              // 0..511
            const int r = idx >> 5, c = idx & 31;       // B: 16 rows x 32 chunks
            CP_ASYNC16(bB[pi] + (uint32_t)(r * HB_P + c * 4) * 4u,
                       Wp + (size_t)(k0 / 2 + r) * N + bn + c * 4);
        }
        CP_COMMIT();
    }

    for (int i = 0; i < 32; i++) {
        const int s = i & 1;
        if (i < 31) { CP_WAIT1(); } else { CP_WAIT0(); }
        __syncthreads();
        const __half* as = Ah[s];
        const uint32_t* bs = Bw[s];
        #pragma unroll
        for (int ks = 0; ks < 2; ks++) {
            uint32_t af[2][4];
            #pragma unroll
            for (int im = 0; im < 2; im++) {
                const __half* p = as + (wm + im * 16 + gID) * HA_P + ks * 16 + 2 * tg;
                af[im][0] = *(const uint32_t*)(p);
                af[im][1] = *(const uint32_t*)(p + 8 * HA_P);
                af[im][2] = *(const uint32_t*)(p + 8);
                af[im][3] = *(const uint32_t*)(p + 8 * HA_P + 8);
            }
            #pragma unroll
            for (int n = 0; n < 8; n++) {
                const uint32_t* bp = bs + (ks * 8 + tg) * HB_P + wn + n * 8 + gID;
                const uint32_t b0 = bp[0];
                const uint32_t b1 = bp[4 * HB_P];
                #pragma unroll
                for (int im = 0; im < 2; im++)
                    mma_f16(acc[im][n][0], acc[im][n][1], acc[im][n][2], acc[im][n][3],
                            af[im][0], af[im][1], af[im][2], af[im][3], b0, b1);
            }
        }
        __syncthreads();
        if (i + 2 < 32) {
            const int k0 = (i + 2) * 32;
            #pragma unroll
            for (int j = 0; j < 2; j++) {
                const int idx = tid + j * 256;
                const int r = idx >> 2, c = idx & 3;
                CP_ASYNC16(aB[s] + (uint32_t)(r * HA_P + c * 8) * 2u,
                           A + (size_t)(bm + r) * D + k0 + c * 8);
            }
            #pragma unroll
            for (int j = 0; j < 2; j++) {
                const int idx = tid + j * 256;
                const int r = idx >> 5, c = idx & 31;
                CP_ASYNC16(bB[s] + (uint32_t)(r * HB_P + c * 4) * 4u,
                           Wp + (size_t)(k0 / 2 + r) * N + bn + c * 4);
            }
            CP_COMMIT();
        }
    }

    // epilogue (acc: rows gID,gID+8; cols 2tg,2tg+1 within n*8 group)
    #pragma unroll
    for (int im = 0; im < 2; im++) {
        const int r0 = bm + wm + im * 16 + gID;
        #pragma unroll
        for (int n = 0; n < 8; n++) {
            const int col = bn + wn + n * 8 + 2 * tg;
            float v0 = acc[im][n][0], v1 = acc[im][n][1];
            float v2 = acc[im][n][2], v3 = acc[im][n][3];
            if (bias) {
                const float b0 = bias[col], b1 = bias[col + 1];
                v0 += b0; v1 += b1; v2 += b0; v3 += b1;
            }
            if (round_out) {
                v0 = tf32r(v0); v1 = tf32r(v1); v2 = tf32r(v2); v3 = tf32r(v3);
            }
            *(float2*)&C[(size_t)r0 * N + col]       = make_float2(v0, v1);
            *(float2*)&C[(size_t)(r0 + 8) * N + col] = make_float2(v2, v3);
        }
    }
}

// ---------------------------------------------------------------------------
// TF32 mma.sync flash attention (R8-good version): register-resident P,
// d-permuted K frags (LDS.128, pitch 80), base-2 softmax (ex2.approx),
// scalar V loads. Epilogue now writes ctx as fp16 for the fp16 out-proj.
// Block: 256 threads / 8 warps, 128 queries (16/warp), 64-key tiles, 2-stage.
// grid (S/128, HEADS, B)
// ---------------------------------------------------------------------------
#define KP 80
#define VP 68
#define K_ST (64 * KP)
#define V_ST (64 * VP)
#define ATTN_SMEM ((2 * K_ST + 2 * V_ST) * 4)   // 75776 B

__global__ __launch_bounds__(256, 2) void attn_kernel(
    const float* __restrict__ qkv, uint32_t* __restrict__ ctxh)
{
    extern __shared__ float sm[];
    float* Ksm[2] = { sm, sm + K_ST };
    float* Vsm[2] = { sm + 2 * K_ST, sm + 2 * K_ST + V_ST };
    const uint32_t kB[2] = { smem_u32(Ksm[0]), smem_u32(Ksm[1]) };
    const uint32_t vB[2] = { smem_u32(Vsm[0]), smem_u32(Vsm[1]) };

    const int tid = threadIdx.x;
    const int wid = tid >> 5, lane = tid & 31;
    const int gID = lane >> 2, tg = lane & 3;
    const int h = blockIdx.y, bb = blockIdx.z;
    const int qbase = blockIdx.x * 128 + wid * 16;

    const float* qp = qkv + (size_t)(bb * S + qbase) * D3 + h * DH;
    const float* kbase = qkv + (size_t)bb * S * D3 + INNER + h * DH;
    const float* vbase = kbase + INNER;

    // Q fragments: d-permuted float4 loads; fold 0.125*log2e, rna-round to tf32
    float4 qf[4][2];
    #pragma unroll
    for (int kg = 0; kg < 4; kg++) {
        float4 v0 = *(const float4*)(qp + (size_t)gID * D3 + kg * 16 + 4 * tg);
        float4 v1 = *(const float4*)(qp + (size_t)(gID + 8) * D3 + kg * 16 + 4 * tg);
        v0.x = tf32r(v0.x * QSCALE_LOG2E); v0.y = tf32r(v0.y * QSCALE_LOG2E);
        v0.z = tf32r(v0.z * QSCALE_LOG2E); v0.w = tf32r(v0.w * QSCALE_LOG2E);
        v1.x = tf32r(v1.x * QSCALE_LOG2E); v1.y = tf32r(v1.y * QSCALE_LOG2E);
        v1.z = tf32r(v1.z * QSCALE_LOG2E); v1.w = tf32r(v1.w * QSCALE_LOG2E);
        qf[kg][0] = v0; qf[kg][1] = v1;
    }

    float o[8][4];
    #pragma unroll
    for (int n = 0; n < 8; n++)
        #pragma unroll
        for (int j = 0; j < 4; j++) o[n][j] = 0.f;
    float m0 = -1e30f, m1 = -1e30f, l0 = 0.f, l1 = 0.f;

    // prologue: tiles 0,1
    #pragma unroll
    for (int pi = 0; pi < 2; pi++) {
        const int r0 = pi * 64;
        #pragma unroll
        for (int j = 0; j < 4; j++) {
            const int idx = tid + j * 256;
            const int r = idx >> 4, c = (idx & 15) * 4;
            CP_ASYNC16(kB[pi] + (uint32_t)(r * KP + c) * 4u,
                       kbase + (size_t)(r0 + r) * D3 + c);
            CP_ASYNC16(vB[pi] + (uint32_t)(r * VP + c) * 4u,
                       vbase + (size_t)(r0 + r) * D3 + c);
        }
        CP_COMMIT();
    }

    for (int i = 0; i < 32; i++) {
        const int s = i & 1;
        if (i < 31) { CP_WAIT1(); } else { CP_WAIT0(); }
        __syncthreads();

        // ---- S = Q @ K^T  (d-permuted fragments, base-2 scaled) ----
        float sa[8][4];
        #pragma unroll
        for (int n = 0; n < 8; n++)
            #pragma unroll
            for (int j = 0; j < 4; j++) sa[n][j] = 0.f;
        const float* ks = Ksm[s];
        #pragma unroll
        for (int kg = 0; kg < 4; kg++) {
            #pragma unroll
            for (int n = 0; n < 8; n++) {
                const float4 kv = *(const float4*)(ks + (n * 8 + gID) * KP + kg * 16 + 4 * tg);
                mma_tf32(sa[n][0], sa[n][1], sa[n][2], sa[n][3],
                         U(qf[kg][0].x), U(qf[kg][1].x), U(qf[kg][0].y), U(qf[kg][1].y),
                         U(kv.x), U(kv.y));
                mma_tf32(sa[n][0], sa[n][1], sa[n][2], sa[n][3],
                         U(qf[kg][0].z), U(qf[kg][1].z), U(qf[kg][0].w), U(qf[kg][1].w),
                         U(kv.z), U(kv.w));
            }
        }

        // ---- online softmax in base 2 (P in registers, tf32-rounded) ----
        float rmax0 = sa[0][0], rmax1 = sa[0][2];
        #pragma unroll
        for (int n = 0; n < 8; n++) {
            rmax0 = fmaxf(rmax0, fmaxf(sa[n][0], sa[n][1]));
            rmax1 = fmaxf(rmax1, fmaxf(sa[n][2], sa[n][3]));
        }
        rmax0 = fmaxf(rmax0, __shfl_xor_sync(0xffffffffu, rmax0, 1));
        rmax0 = fmaxf(rmax0, __shfl_xor_sync(0xffffffffu, rmax0, 2));
        rmax1 = fmaxf(rmax1, __shfl_xor_sync(0xffffffffu, rmax1, 1));
        rmax1 = fmaxf(rmax1, __shfl_xor_sync(0xffffffffu, rmax1, 2));
        const float nm0 = fmaxf(m0, rmax0), nm1 = fmaxf(m1, rmax1);
        const float c0 = ex2f(m0 - nm0), c1 = ex2f(m1 - nm1);
        m0 = nm0; m1 = nm1;
        float s0 = 0.f, s1 = 0.f;
        #pragma unroll
        for (int n = 0; n < 8; n++) {
            const float p0 = ex2f(sa[n][0] - m0);
            const float p1 = ex2f(sa[n][1] - m0);
            const float p2 = ex2f(sa[n][2] - m1);
            const float p3 = ex2f(sa[n][3] - m1);
            s0 += p0 + p1; s1 += p2 + p3;
            sa[n][0] = tf32r(p0); sa[n][1] = tf32r(p1);
            sa[n][2] = tf32r(p2); sa[n][3] = tf32r(p3);
            o[n][0] *= c0; o[n][1] *= c0; o[n][2] *= c1; o[n][3] *= c1;
        }
        s0 += __shfl_xor_sync(0xffffffffu, s0, 1);
        s0 += __shfl_xor_sync(0xffffffffu, s0, 2);
        s1 += __shfl_xor_sync(0xffffffffu, s1, 1);
        s1 += __shfl_xor_sync(0xffffffffu, s1, 2);
        l0 = l0 * c0 + s0;
        l1 = l1 * c1 + s1;

        // ---- O += P @ V  (key-relabel: S acc IS the A fragment) ----
        const float* vs = Vsm[s];
        #pragma unroll
        for (int kf = 0; kf < 8; kf++) {
            const uint32_t a0 = U(sa[kf][0]);
            const uint32_t a1 = U(sa[kf][2]);
            const uint32_t a2 = U(sa[kf][1]);
            const uint32_t a3 = U(sa[kf][3]);
            #pragma unroll
            for (int n = 0; n < 8; n++) {
                const float* bp = vs + (kf * 8 + 2 * tg) * VP + n * 8 + gID;
                mma_tf32(o[n][0], o[n][1], o[n][2], o[n][3],
                         a0, a1, a2, a3,
                         U(bp[0]), U(bp[VP]));
            }
        }
        __syncthreads();

        if (i + 2 < 32) {
            const int r0 = (i + 2) * 64;
            #pragma unroll
            for (int j = 0; j < 4; j++) {
                const int idx = tid + j * 256;
                const int r = idx >> 4, c = (idx & 15) * 4;
                CP_ASYNC16(kB[s] + (uint32_t)(r * KP + c) * 4u,
                           kbase + (size_t)(r0 + r) * D3 + c);
                CP_ASYNC16(vB[s] + (uint32_t)(r * VP + c) * 4u,
                           vbase + (size_t)(r0 + r) * D3 + c);
            }
            CP_COMMIT();
        }
    }

    // epilogue: normalize, write fp16 half2 pairs (consumed by fp16 out-proj)
    const float inv0 = 1.f / l0, inv1 = 1.f / l1;
    const size_t grow = (size_t)(bb * S + qbase + gID);
    #pragma unroll
    for (int n = 0; n < 8; n++) {
        const int col = h * DH + n * 8 + 2 * tg;     // even
        ctxh[(grow * INNER + col) >> 1] =
            packh2(o[n][0] * inv0, o[n][1] * inv0);
        ctxh[((grow + 8) * INNER + col) >> 1] =
            packh2(o[n][2] * inv1, o[n][3] * inv1);
    }
}

// ---------------------------------------------------------------------------
extern "C" void kernel_launch(void* const* d_in, const int* in_sizes, int n_in,
                              void* d_out, int out_size)
{
    const float* x        = (const float*)d_in[0];
    const float* ln_gamma = (const float*)d_in[1];
    const float* ln_beta  = (const float*)d_in[2];
    const float* w_qkv    = (const float*)d_in[3];
    const float* w_out    = (const float*)d_in[4];
    const float* b_out    = (const float*)d_in[5];
    float* out = (float*)d_out;

    void* sp = nullptr;
    cudaGetSymbolAddress(&sp, g_scratch);
    float* base = (float*)sp;
    uint32_t* xnh  = (uint32_t*)base;                       // ROWS*D halves
    float*    qkv  = base + (size_t)ROWS * D / 2;           // ROWS*D3 f32
    uint32_t* ctxh = (uint32_t*)(qkv + (size_t)ROWS * D3);  // ROWS*D halves
    uint32_t* wqh  = ctxh + (size_t)ROWS * D / 2;           // 512*D3 u32
    uint32_t* woh  = wqh + (size_t)512 * D3;                // 512*D u32

    cudaFuncSetAttribute(gemm_h_kernel, cudaFuncAttributeMaxDynamicSharedMemorySize, GEMM_SMEM);
    cudaFuncSetAttribute(attn_kernel, cudaFuncAttributeMaxDynamicSharedMemorySize, ATTN_SMEM);

    // pack weights to fp16 k-pair layout
    pack_w_kernel<<<(512 * (D3 / 4) + 255) / 256, 256>>>(w_qkv, wqh, D3);
    pack_w_kernel<<<(512 * (D / 4) + 255) / 256, 256>>>(w_out, woh, D);

    // 1. LayerNorm (fp16 output)
    ln_kernel<<<ROWS, 256>>>(x, ln_gamma, ln_beta, xnh);

    // 2. QKV projection (fp16 tensor cores, tf32-rounded fp32 output)
    gemm_h_kernel<<<dim3(D3 / 128, ROWS / 128), 256, GEMM_SMEM>>>(
        (const __half*)xnh, wqh, nullptr, qkv, D3, 1);

    // 3. Flash attention (tf32 tensor cores, register P, fp16 ctx output)
    attn_kernel<<<dim3(S / 128, HEADS, B), 256, ATTN_SMEM>>>(qkv, ctxh);

    // 4. Output projection + bias (fp16 tensor cores, fp32 out)
    gemm_h_kernel<<<dim3(D / 128, ROWS / 128), 256, GEMM_SMEM>>>(
        (const __half*)ctxh, woh, b_out, out, D, 0);
}

// round 11
// speedup vs baseline: 1.9828x; 1.4338x over previous
#include <cuda_runtime.h>
#include <cuda_fp16.h>
#include <cstdint>
#include <math.h>

// Problem constants
#define B       2
#define S       2048
#define D       1024
#define HEADS   16
#define DH      64
#define INNER   1024
#define D3      3072
#define ROWS    4096
#define LN_EPS  1e-5f
// 0.125 * log2(e): applied to S inside softmax (fma), Q stays raw fp16
#define QSCALE_LOG2E 0.18033688011112042f

// Scratch: xn(half) | qkv(half) | ctx(half) | w_qkv packed | w_out packed
__device__ float g_scratch[(size_t)ROWS * D + (size_t)ROWS * D3 + (size_t)ROWS * D
                           + (size_t)D * D3 + (size_t)D * D];

// ---------------------------------------------------------------------------
// Helpers
// ---------------------------------------------------------------------------
__device__ __forceinline__ uint32_t smem_u32(const void* p) {
    uint32_t a;
    asm("{ .reg .u64 t; cvta.to.shared.u64 t, %1; cvt.u32.u64 %0, t; }" : "=r"(a) : "l"(p));
    return a;
}
__device__ __forceinline__ float ex2f(float x) {
    float r;
    asm("ex2.approx.ftz.f32 %0, %1;" : "=f"(r) : "f"(x));
    return r;
}
__device__ __forceinline__ uint32_t packh2(float lo, float hi) {
    __half2 h = __floats2half2_rn(lo, hi);
    return *(uint32_t*)&h;
}

#define CP_ASYNC16(dst, src) \
    asm volatile("cp.async.cg.shared.global [%0], [%1], 16;" :: "r"(dst), "l"(src))
#define CP_COMMIT()  asm volatile("cp.async.commit_group;" ::: "memory")
#define CP_WAIT1()   asm volatile("cp.async.wait_group 1;" ::: "memory")
#define CP_WAIT0()   asm volatile("cp.async.wait_group 0;" ::: "memory")

__device__ __forceinline__ void mma_f16(
    float& d0, float& d1, float& d2, float& d3,
    uint32_t a0, uint32_t a1, uint32_t a2, uint32_t a3,
    uint32_t b0, uint32_t b1)
{
    asm volatile(
        "mma.sync.aligned.m16n8k16.row.col.f32.f16.f16.f32 "
        "{%0,%1,%2,%3}, {%4,%5,%6,%7}, {%8,%9}, {%0,%1,%2,%3};"
        : "+f"(d0), "+f"(d1), "+f"(d2), "+f"(d3)
        : "r"(a0), "r"(a1), "r"(a2), "r"(a3), "r"(b0), "r"(b1));
}
#define LDSM_X4(r0, r1, r2, r3, addr) \
    asm volatile("ldmatrix.sync.aligned.m8n8.x4.shared.b16 {%0,%1,%2,%3}, [%4];" \
        : "=r"(r0), "=r"(r1), "=r"(r2), "=r"(r3) : "r"(addr))
#define LDSM_X4_T(r0, r1, r2, r3, addr) \
    asm volatile("ldmatrix.sync.aligned.m8n8.x4.trans.shared.b16 {%0,%1,%2,%3}, [%4];" \
        : "=r"(r0), "=r"(r1), "=r"(r2), "=r"(r3) : "r"(addr))

// ---------------------------------------------------------------------------
// LayerNorm (output written as fp16, rn)
// ---------------------------------------------------------------------------
__global__ __launch_bounds__(256) void ln_kernel(
    const float* __restrict__ x, const float* __restrict__ gamma,
    const float* __restrict__ beta, uint32_t* __restrict__ y)
{
    const int row = blockIdx.x;
    const int t = threadIdx.x;
    const float4* xp = (const float4*)(x + (size_t)row * D);
    float4 v = xp[t];
    float s  = v.x + v.y + v.z + v.w;
    float ss = v.x * v.x + v.y * v.y + v.z * v.z + v.w * v.w;
    #pragma unroll
    for (int off = 16; off > 0; off >>= 1) {
        s  += __shfl_down_sync(0xffffffffu, s,  off);
        ss += __shfl_down_sync(0xffffffffu, ss, off);
    }
    __shared__ float sh_s[8], sh_ss[8];
    const int w = t >> 5, lane = t & 31;
    if (lane == 0) { sh_s[w] = s; sh_ss[w] = ss; }
    __syncthreads();
    __shared__ float mu_sh, rstd_sh;
    if (t == 0) {
        float S0 = 0.f, SS0 = 0.f;
        #pragma unroll
        for (int i = 0; i < 8; i++) { S0 += sh_s[i]; SS0 += sh_ss[i]; }
        const float mu  = S0 * (1.0f / D);
        const float var = SS0 * (1.0f / D) - mu * mu;
        mu_sh = mu;
        rstd_sh = rsqrtf(var + LN_EPS);
    }
    __syncthreads();
    const float mu = mu_sh, rstd = rstd_sh;
    float4 g  = ((const float4*)gamma)[t];
    float4 bb = ((const float4*)beta)[t];
    const float ox = (v.x - mu) * rstd * g.x + bb.x;
    const float oy = (v.y - mu) * rstd * g.y + bb.y;
    const float oz = (v.z - mu) * rstd * g.z + bb.z;
    const float ow = (v.w - mu) * rstd * g.w + bb.w;
    ((uint2*)(y + (size_t)row * (D / 2)))[t] = make_uint2(packh2(ox, oy), packh2(oz, ow));
}

// ---------------------------------------------------------------------------
// Pack weights: W[K=1024][N] f32 -> Wp[j=K/2][N] u32 (fp16 k-pair layout)
// ---------------------------------------------------------------------------
__global__ __launch_bounds__(256) void pack_w_kernel(
    const float* __restrict__ W, uint32_t* __restrict__ Wp, int N)
{
    const int n4 = N >> 2;
    const int idx = blockIdx.x * 256 + threadIdx.x;
    if (idx >= 512 * n4) return;
    const int j = idx / n4, c = idx - j * n4;
    const float4 r0 = *(const float4*)(W + (size_t)(2 * j) * N + c * 4);
    const float4 r1 = *(const float4*)(W + (size_t)(2 * j + 1) * N + c * 4);
    uint4 o;
    o.x = packh2(r0.x, r1.x); o.y = packh2(r0.y, r1.y);
    o.z = packh2(r0.z, r1.z); o.w = packh2(r0.w, r1.w);
    *(uint4*)(Wp + (size_t)j * N + c * 4) = o;
}

// ---------------------------------------------------------------------------
// FP16 mma.sync GEMM: C = A[M,1024] @ W (+bias), f32 accumulate.
// Output: fp32 (Cf) or packed fp16 (Ch). 128x128 tile, BK=32, 256 threads.
// ---------------------------------------------------------------------------
#define HA_P 40
#define HB_P 136
#define HA_ST (128 * HA_P)          // halves per A stage
#define HB_ST (16 * HB_P)           // u32 per B stage
#define GEMM_SMEM (2 * (HA_ST * 2 + HB_ST * 4))   // 37888 B

__global__ __launch_bounds__(256, 2) void gemm_h_kernel(
    const __half* __restrict__ A, const uint32_t* __restrict__ Wp,
    const float* __restrict__ bias, float* __restrict__ Cf,
    uint32_t* __restrict__ Ch, int N)
{
    extern __shared__ char smc[];
    __half* Ah[2]    = { (__half*)smc, (__half*)smc + HA_ST };
    uint32_t* Bw[2]  = { (uint32_t*)(smc + 2 * HA_ST * 2),
                         (uint32_t*)(smc + 2 * HA_ST * 2) + HB_ST };
    const uint32_t aB[2] = { smem_u32(Ah[0]), smem_u32(Ah[1]) };
    const uint32_t bB[2] = { smem_u32(Bw[0]), smem_u32(Bw[1]) };

    const int tid = threadIdx.x;
    const int wid = tid >> 5, lane = tid & 31;
    const int gID = lane >> 2, tg = lane & 3;
    const int bm = blockIdx.y * 128, bn = blockIdx.x * 128;
    const int wm = (wid & 3) * 32, wn = (wid >> 2) * 64;

    float acc[2][8][4];
    #pragma unroll
    for (int im = 0; im < 2; im++)
        #pragma unroll
        for (int n = 0; n < 8; n++)
            #pragma unroll
            for (int j = 0; j < 4; j++) acc[im][n][j] = 0.f;

    // prologue: chunks 0,1
    #pragma unroll
    for (int pi = 0; pi < 2; pi++) {
        const int k0 = pi * 32;
        #pragma unroll
        for (int j = 0; j < 2; j++) {
            const int idx = tid + j * 256;
            const int r = idx >> 2, c = idx & 3;
            CP_ASYNC16(aB[pi] + (uint32_t)(r * HA_P + c * 8) * 2u,
                       A + (size_t)(bm + r) * D + k0 + c * 8);
        }
        #pragma unroll
        for (int j = 0; j < 2; j++) {
            const int idx = tid + j * 256;
            const int r = idx >> 5, c = idx & 31;
            CP_ASYNC16(bB[pi] + (uint32_t)(r * HB_P + c * 4) * 4u,
                       Wp + (size_t)(k0 / 2 + r) * N + bn + c * 4);
        }
        CP_COMMIT();
    }

    for (int i = 0; i < 32; i++) {
        const int s = i & 1;
        if (i < 31) { CP_WAIT1(); } else { CP_WAIT0(); }
        __syncthreads();
        const __half* as = Ah[s];
        const uint32_t* bs = Bw[s];
        #pragma unroll
        for (int ks = 0; ks < 2; ks++) {
            uint32_t af[2][4];
            #pragma unroll
            for (int im = 0; im < 2; im++) {
                const __half* p = as + (wm + im * 16 + gID) * HA_P + ks * 16 + 2 * tg;
                af[im][0] = *(const uint32_t*)(p);
                af[im][1] = *(const uint32_t*)(p + 8 * HA_P);
                af[im][2] = *(const uint32_t*)(p + 8);
                af[im][3] = *(const uint32_t*)(p + 8 * HA_P + 8);
            }
            #pragma unroll
            for (int n = 0; n < 8; n++) {
                const uint32_t* bp = bs + (ks * 8 + tg) * HB_P + wn + n * 8 + gID;
                const uint32_t b0 = bp[0];
                const uint32_t b1 = bp[4 * HB_P];
                #pragma unroll
                for (int im = 0; im < 2; im++)
                    mma_f16(acc[im][n][0], acc[im][n][1], acc[im][n][2], acc[im][n][3],
                            af[im][0], af[im][1], af[im][2], af[im][3], b0, b1);
            }
        }
        __syncthreads();
        if (i + 2 < 32) {
            const int k0 = (i + 2) * 32;
            #pragma unroll
            for (int j = 0; j < 2; j++) {
                const int idx = tid + j * 256;
                const int r = idx >> 2, c = idx & 3;
                CP_ASYNC16(aB[s] + (uint32_t)(r * HA_P + c * 8) * 2u,
                           A + (size_t)(bm + r) * D + k0 + c * 8);
            }
            #pragma unroll
            for (int j = 0; j < 2; j++) {
                const int idx = tid + j * 256;
                const int r = idx >> 5, c = idx & 31;
                CP_ASYNC16(bB[s] + (uint32_t)(r * HB_P + c * 4) * 4u,
                           Wp + (size_t)(k0 / 2 + r) * N + bn + c * 4);
            }
            CP_COMMIT();
        }
    }

    // epilogue
    #pragma unroll
    for (int im = 0; im < 2; im++) {
        const int r0 = bm + wm + im * 16 + gID;
        #pragma unroll
        for (int n = 0; n < 8; n++) {
            const int col = bn + wn + n * 8 + 2 * tg;
            float v0 = acc[im][n][0], v1 = acc[im][n][1];
            float v2 = acc[im][n][2], v3 = acc[im][n][3];
            if (bias) {
                const float b0 = bias[col], b1 = bias[col + 1];
                v0 += b0; v1 += b1; v2 += b0; v3 += b1;
            }
            if (Ch) {
                Ch[((size_t)r0 * N + col) >> 1]       = packh2(v0, v1);
                Ch[((size_t)(r0 + 8) * N + col) >> 1] = packh2(v2, v3);
            } else {
                *(float2*)&Cf[(size_t)r0 * N + col]       = make_float2(v0, v1);
                *(float2*)&Cf[(size_t)(r0 + 8) * N + col] = make_float2(v2, v3);
            }
        }
    }
}

// ---------------------------------------------------------------------------
// FP16 mma.sync flash attention.
//  - Q/K/V fp16 (from fp16 QKV gemm); S,O accumulate fp32
//  - K fragments via ldmatrix.x4 (row-major K == col-major B)
//  - V fragments via ldmatrix.x4.trans (HW key-pair packing)
//  - P A-fragments = packed half2 of S accumulators (natural layout)
//  - base-2 softmax; scale folded via fma(s, 0.125*log2e, -m)
// Block: 256 threads / 8 warps, 128 queries (16/warp), 64-key tiles, 2-stage.
// grid (S/128, HEADS, B).  smem pitch 72 halves (36 u32): ldmatrix
// phase banks = 4r+c, conflict-free.
// ---------------------------------------------------------------------------
#define KPH 72
#define KV_TILE_B (64 * KPH * 2)            // 9216 B per K or V stage
#define ATTN_SMEM (2 * 2 * KV_TILE_B)       // 36864 B

__global__ __launch_bounds__(256, 2) void attn_kernel(
    const __half* __restrict__ qkv, uint32_t* __restrict__ ctxh)
{
    extern __shared__ char smc[];
    const uint32_t kB[2] = { smem_u32(smc),                 smem_u32(smc) + KV_TILE_B };
    const uint32_t vB[2] = { kB[0] + 2 * KV_TILE_B,         kB[1] + 2 * KV_TILE_B };

    const int tid = threadIdx.x;
    const int wid = tid >> 5, lane = tid & 31;
    const int gID = lane >> 2, tg = lane & 3;
    const int rowl = lane & 7, grp = lane >> 3;
    const int h = blockIdx.y, bb = blockIdx.z;
    const int qbase = blockIdx.x * 128 + wid * 16;

    const __half* qp = qkv + (size_t)(bb * S + qbase) * D3 + h * DH;
    const __half* kbase = qkv + (size_t)bb * S * D3 + INNER + h * DH;
    const __half* vbase = kbase + INNER;

    // Q fragments: raw fp16, u32 pair slots (8ks+tg, 8ks+4+tg) per row
    uint32_t qa[4][4];
    #pragma unroll
    for (int ks = 0; ks < 4; ks++) {
        qa[ks][0] = *(const uint32_t*)(qp + (size_t)gID * D3 + 16 * ks + 2 * tg);
        qa[ks][1] = *(const uint32_t*)(qp + (size_t)(gID + 8) * D3 + 16 * ks + 2 * tg);
        qa[ks][2] = *(const uint32_t*)(qp + (size_t)gID * D3 + 16 * ks + 2 * tg + 8);
        qa[ks][3] = *(const uint32_t*)(qp + (size_t)(gID + 8) * D3 + 16 * ks + 2 * tg + 8);
    }

    // per-lane ldmatrix base offsets (bytes)
    // S-stage (K, non-trans): tiles r0..r3 = (klo,ne),(khi,ne),(klo,no),(khi,no)
    const uint32_t k_lane_off = (uint32_t)((((grp >> 1) * 8 + rowl) * KPH + (grp & 1) * 8) * 2);
    // PV (V, trans): tiles r0..r3 = (keylo,ce),(keyhi,ce),(keylo,co),(keyhi,co)
    const uint32_t v_lane_off = (uint32_t)((((grp & 1) * 8 + rowl) * KPH + (grp >> 1) * 8) * 2);

    float o[8][4];
    #pragma unroll
    for (int n = 0; n < 8; n++)
        #pragma unroll
        for (int j = 0; j < 4; j++) o[n][j] = 0.f;
    float m0 = -1e30f, m1 = -1e30f, l0 = 0.f, l1 = 0.f;
    const float CS = QSCALE_LOG2E;

    // prologue: tiles 0,1  (K and V rows: 64 x 64 halves, 8 chunks of 16B)
    #pragma unroll
    for (int pi = 0; pi < 2; pi++) {
        const int r0 = pi * 64;
        #pragma unroll
        for (int j = 0; j < 2; j++) {
            const int idx = tid + j * 256;
            const int r = idx >> 3, c = idx & 7;
            CP_ASYNC16(kB[pi] + (uint32_t)(r * KPH + c * 8) * 2u,
                       kbase + (size_t)(r0 + r) * D3 + c * 8);
            CP_ASYNC16(vB[pi] + (uint32_t)(r * KPH + c * 8) * 2u,
                       vbase + (size_t)(r0 + r) * D3 + c * 8);
        }
        CP_COMMIT();
    }

    for (int i = 0; i < 32; i++) {
        const int s = i & 1;
        if (i < 31) { CP_WAIT1(); } else { CP_WAIT0(); }
        __syncthreads();

        // ---- S = Q @ K^T (fp16 mma, ldmatrix K fragments) ----
        float sa[8][4];
        #pragma unroll
        for (int n = 0; n < 8; n++)
            #pragma unroll
            for (int j = 0; j < 4; j++) sa[n][j] = 0.f;
        #pragma unroll
        for (int ks = 0; ks < 4; ks++) {
            #pragma unroll
            for (int np = 0; np < 4; np++) {
                uint32_t r0, r1, r2, r3;
                LDSM_X4(r0, r1, r2, r3,
                        kB[s] + k_lane_off + (uint32_t)((np * 16 * KPH + ks * 16) * 2));
                mma_f16(sa[2*np][0], sa[2*np][1], sa[2*np][2], sa[2*np][3],
                        qa[ks][0], qa[ks][1], qa[ks][2], qa[ks][3], r0, r1);
                mma_f16(sa[2*np+1][0], sa[2*np+1][1], sa[2*np+1][2], sa[2*np+1][3],
                        qa[ks][0], qa[ks][1], qa[ks][2], qa[ks][3], r2, r3);
            }
        }

        // ---- online softmax (base 2, scale via fma; P packed to half2) ----
        float rmax0 = sa[0][0], rmax1 = sa[0][2];
        #pragma unroll
        for (int n = 0; n < 8; n++) {
            rmax0 = fmaxf(rmax0, fmaxf(sa[n][0], sa[n][1]));
            rmax1 = fmaxf(rmax1, fmaxf(sa[n][2], sa[n][3]));
        }
        rmax0 = fmaxf(rmax0, __shfl_xor_sync(0xffffffffu, rmax0, 1));
        rmax0 = fmaxf(rmax0, __shfl_xor_sync(0xffffffffu, rmax0, 2));
        rmax1 = fmaxf(rmax1, __shfl_xor_sync(0xffffffffu, rmax1, 1));
        rmax1 = fmaxf(rmax1, __shfl_xor_sync(0xffffffffu, rmax1, 2));
        const float nm0 = fmaxf(m0, rmax0 * CS), nm1 = fmaxf(m1, rmax1 * CS);
        const float c0 = ex2f(m0 - nm0), c1 = ex2f(m1 - nm1);
        m0 = nm0; m1 = nm1;
        float s0 = 0.f, s1 = 0.f;
        uint32_t p01[8], p23[8];
        #pragma unroll
        for (int n = 0; n < 8; n++) {
            const float p0 = ex2f(fmaf(sa[n][0], CS, -m0));
            const float p1 = ex2f(fmaf(sa[n][1], CS, -m0));
            const float p2 = ex2f(fmaf(sa[n][2], CS, -m1));
            const float p3 = ex2f(fmaf(sa[n][3], CS, -m1));
            s0 += p0 + p1; s1 += p2 + p3;
            p01[n] = packh2(p0, p1);
            p23[n] = packh2(p2, p3);
            o[n][0] *= c0; o[n][1] *= c0; o[n][2] *= c1; o[n][3] *= c1;
        }
        s0 += __shfl_xor_sync(0xffffffffu, s0, 1);
        s0 += __shfl_xor_sync(0xffffffffu, s0, 2);
        s1 += __shfl_xor_sync(0xffffffffu, s1, 1);
        s1 += __shfl_xor_sync(0xffffffffu, s1, 2);
        l0 = l0 * c0 + s0;
        l1 = l1 * c1 + s1;

        // ---- O += P @ V (fp16 mma, ldmatrix.trans V fragments) ----
        #pragma unroll
        for (int kc = 0; kc < 4; kc++) {
            const uint32_t a0 = p01[2*kc], a1 = p23[2*kc];
            const uint32_t a2 = p01[2*kc+1], a3 = p23[2*kc+1];
            #pragma unroll
            for (int cp = 0; cp < 4; cp++) {
                uint32_t r0, r1, r2, r3;
                LDSM_X4_T(r0, r1, r2, r3,
                          vB[s] + v_lane_off + (uint32_t)((kc * 16 * KPH + cp * 16) * 2));
                mma_f16(o[2*cp][0], o[2*cp][1], o[2*cp][2], o[2*cp][3],
                        a0, a1, a2, a3, r0, r1);
                mma_f16(o[2*cp+1][0], o[2*cp+1][1], o[2*cp+1][2], o[2*cp+1][3],
                        a0, a1, a2, a3, r2, r3);
            }
        }
        __syncthreads();

        if (i + 2 < 32) {
            const int r0 = (i + 2) * 64;
            #pragma unroll
            for (int j = 0; j < 2; j++) {
                const int idx = tid + j * 256;
                const int r = idx >> 3, c = idx & 7;
                CP_ASYNC16(kB[s] + (uint32_t)(r * KPH + c * 8) * 2u,
                           kbase + (size_t)(r0 + r) * D3 + c * 8);
                CP_ASYNC16(vB[s] + (uint32_t)(r * KPH + c * 8) * 2u,
                           vbase + (size_t)(r0 + r) * D3 + c * 8);
            }
            CP_COMMIT();
        }
    }

    // epilogue: normalize, write fp16 half2 pairs (consumed by fp16 out-proj)
    const float inv0 = 1.f / l0, inv1 = 1.f / l1;
    const size_t grow = (size_t)(bb * S + qbase + gID);
    #pragma unroll
    for (int n = 0; n < 8; n++) {
        const int col = h * DH + n * 8 + 2 * tg;     // even
        ctxh[(grow * INNER + col) >> 1] =
            packh2(o[n][0] * inv0, o[n][1] * inv0);
        ctxh[((grow + 8) * INNER + col) >> 1] =
            packh2(o[n][2] * inv1, o[n][3] * inv1);
    }
}

// ---------------------------------------------------------------------------
extern "C" void kernel_launch(void* const* d_in, const int* in_sizes, int n_in,
                              void* d_out, int out_size)
{
    const float* x        = (const float*)d_in[0];
    const float* ln_gamma = (const float*)d_in[1];
    const float* ln_beta  = (const float*)d_in[2];
    const float* w_qkv    = (const float*)d_in[3];
    const float* w_out    = (const float*)d_in[4];
    const float* b_out    = (const float*)d_in[5];
    float* out = (float*)d_out;

    void* sp = nullptr;
    cudaGetSymbolAddress(&sp, g_scratch);
    float* base = (float*)sp;
    uint32_t* xnh  = (uint32_t*)base;                        // ROWS*D halves
    uint32_t* qkvh = xnh + (size_t)ROWS * D / 2;             // ROWS*D3 halves
    uint32_t* ctxh = qkvh + (size_t)ROWS * D3 / 2;           // ROWS*D halves
    uint32_t* wqh  = ctxh + (size_t)ROWS * D / 2;            // 512*D3 u32
    uint32_t* woh  = wqh + (size_t)512 * D3;                 // 512*D u32

    cudaFuncSetAttribute(gemm_h_kernel, cudaFuncAttributeMaxDynamicSharedMemorySize, GEMM_SMEM);
    cudaFuncSetAttribute(attn_kernel, cudaFuncAttributeMaxDynamicSharedMemorySize, ATTN_SMEM);

    // pack weights to fp16 k-pair layout
    pack_w_kernel<<<(512 * (D3 / 4) + 255) / 256, 256>>>(w_qkv, wqh, D3);
    pack_w_kernel<<<(512 * (D / 4) + 255) / 256, 256>>>(w_out, woh, D);

    // 1. LayerNorm (fp16 output)
    ln_kernel<<<ROWS, 256>>>(x, ln_gamma, ln_beta, xnh);

    // 2. QKV projection (fp16 tensor cores, fp16 output)
    gemm_h_kernel<<<dim3(D3 / 128, ROWS / 128), 256, GEMM_SMEM>>>(
        (const __half*)xnh, wqh, nullptr, nullptr, qkvh, D3);

    // 3. Flash attention (fp16 tensor cores + ldmatrix, fp16 ctx output)
    attn_kernel<<<dim3(S / 128, HEADS, B), 256, ATTN_SMEM>>>(
        (const __half*)qkvh, ctxh);

    // 4. Output projection + bias (fp16 tensor cores, fp32 out)
    gemm_h_kernel<<<dim3(D / 128, ROWS / 128), 256, GEMM_SMEM>>>(
        (const __half*)ctxh, woh, b_out, out, nullptr, D);
}

// round 12
// speedup vs baseline: 2.0599x; 1.0389x over previous
#include <cuda_runtime.h>
#include <cuda_fp16.h>
#include <cstdint>
#include <math.h>

// Problem constants
#define B       2
#define S       2048
#define D       1024
#define HEADS   16
#define DH      64
#define INNER   1024
#define D3      3072
#define ROWS    4096
#define LN_EPS  1e-5f
// 0.125 * log2(e): applied to S inside softmax (fma), Q stays raw fp16
#define QSCALE_LOG2E 0.18033688011112042f

// Scratch: xn(half) | qkv(half) | ctx(half) | w_qkv^T(half) | w_out^T(half)
__device__ float g_scratch[(size_t)ROWS * D + (size_t)ROWS * D3 + (size_t)ROWS * D
                           + (size_t)D * D3 + (size_t)D * D];

// ---------------------------------------------------------------------------
// Helpers
// ---------------------------------------------------------------------------
__device__ __forceinline__ uint32_t smem_u32(const void* p) {
    uint32_t a;
    asm("{ .reg .u64 t; cvta.to.shared.u64 t, %1; cvt.u32.u64 %0, t; }" : "=r"(a) : "l"(p));
    return a;
}
__device__ __forceinline__ float ex2f(float x) {
    float r;
    asm("ex2.approx.ftz.f32 %0, %1;" : "=f"(r) : "f"(x));
    return r;
}
__device__ __forceinline__ uint32_t packh2(float lo, float hi) {
    __half2 h = __floats2half2_rn(lo, hi);
    return *(uint32_t*)&h;
}

#define CP_ASYNC16(dst, src) \
    asm volatile("cp.async.cg.shared.global [%0], [%1], 16;" :: "r"(dst), "l"(src))
#define CP_COMMIT()  asm volatile("cp.async.commit_group;" ::: "memory")
#define CP_WAIT1()   asm volatile("cp.async.wait_group 1;" ::: "memory")
#define CP_WAIT0()   asm volatile("cp.async.wait_group 0;" ::: "memory")

__device__ __forceinline__ void mma_f16(
    float& d0, float& d1, float& d2, float& d3,
    uint32_t a0, uint32_t a1, uint32_t a2, uint32_t a3,
    uint32_t b0, uint32_t b1)
{
    asm volatile(
        "mma.sync.aligned.m16n8k16.row.col.f32.f16.f16.f32 "
        "{%0,%1,%2,%3}, {%4,%5,%6,%7}, {%8,%9}, {%0,%1,%2,%3};"
        : "+f"(d0), "+f"(d1), "+f"(d2), "+f"(d3)
        : "r"(a0), "r"(a1), "r"(a2), "r"(a3), "r"(b0), "r"(b1));
}
#define LDSM_X4(r0, r1, r2, r3, addr) \
    asm volatile("ldmatrix.sync.aligned.m8n8.x4.shared.b16 {%0,%1,%2,%3}, [%4];" \
        : "=r"(r0), "=r"(r1), "=r"(r2), "=r"(r3) : "r"(addr))
#define LDSM_X4_T(r0, r1, r2, r3, addr) \
    asm volatile("ldmatrix.sync.aligned.m8n8.x4.trans.shared.b16 {%0,%1,%2,%3}, [%4];" \
        : "=r"(r0), "=r"(r1), "=r"(r2), "=r"(r3) : "r"(addr))

// ---------------------------------------------------------------------------
// LayerNorm (output written as fp16, rn)
// ---------------------------------------------------------------------------
__global__ __launch_bounds__(256) void ln_kernel(
    const float* __restrict__ x, const float* __restrict__ gamma,
    const float* __restrict__ beta, uint32_t* __restrict__ y)
{
    const int row = blockIdx.x;
    const int t = threadIdx.x;
    const float4* xp = (const float4*)(x + (size_t)row * D);
    float4 v = xp[t];
    float s  = v.x + v.y + v.z + v.w;
    float ss = v.x * v.x + v.y * v.y + v.z * v.z + v.w * v.w;
    #pragma unroll
    for (int off = 16; off > 0; off >>= 1) {
        s  += __shfl_down_sync(0xffffffffu, s,  off);
        ss += __shfl_down_sync(0xffffffffu, ss, off);
    }
    __shared__ float sh_s[8], sh_ss[8];
    const int w = t >> 5, lane = t & 31;
    if (lane == 0) { sh_s[w] = s; sh_ss[w] = ss; }
    __syncthreads();
    __shared__ float mu_sh, rstd_sh;
    if (t == 0) {
        float S0 = 0.f, SS0 = 0.f;
        #pragma unroll
        for (int i = 0; i < 8; i++) { S0 += sh_s[i]; SS0 += sh_ss[i]; }
        const float mu  = S0 * (1.0f / D);
        const float var = SS0 * (1.0f / D) - mu * mu;
        mu_sh = mu;
        rstd_sh = rsqrtf(var + LN_EPS);
    }
    __syncthreads();
    const float mu = mu_sh, rstd = rstd_sh;
    float4 g  = ((const float4*)gamma)[t];
    float4 bb = ((const float4*)beta)[t];
    const float ox = (v.x - mu) * rstd * g.x + bb.x;
    const float oy = (v.y - mu) * rstd * g.y + bb.y;
    const float oz = (v.z - mu) * rstd * g.z + bb.z;
    const float ow = (v.w - mu) * rstd * g.w + bb.w;
    ((uint2*)(y + (size_t)row * (D / 2)))[t] = make_uint2(packh2(ox, oy), packh2(oz, ow));
}

// ---------------------------------------------------------------------------
// Pack + transpose weights: W[K=1024][N] f32 -> WT[N][K=1024] fp16.
// grid (N/32, 32), block (32, 8)
// ---------------------------------------------------------------------------
__global__ __launch_bounds__(256) void pack_wT_kernel(
    const float* __restrict__ W, __half* __restrict__ WT, int N)
{
    __shared__ float tile[32][33];
    const int n0 = blockIdx.x * 32, k0 = blockIdx.y * 32;
    const int tx = threadIdx.x, ty = threadIdx.y;
    #pragma unroll
    for (int j = 0; j < 32; j += 8)
        tile[ty + j][tx] = W[(size_t)(k0 + ty + j) * N + n0 + tx];
    __syncthreads();
    #pragma unroll
    for (int j = 0; j < 32; j += 8)
        WT[(size_t)(n0 + ty + j) * D + k0 + tx] = __float2half_rn(tile[tx][ty + j]);
}

// ---------------------------------------------------------------------------
// FP16 mma.sync GEMM with ldmatrix fragments:
// C = A[M,1024] @ WT[N,1024]^T (+bias), f32 accumulate.
// A, WT both fp16 row-major with contiguous K. 128x128 tile, BK=32,
// 256 threads, 8 warps (warp-tile 32x64), cp.async double-buffered.
// smem pitch 40 halves: per-8-lane ldmatrix phase covers banks 20r..20r+3
// = all 32, conflict-free.
// Output: fp32 (Cf) or packed fp16 (Ch).
// ---------------------------------------------------------------------------
#define GP 40
#define G_ST (128 * GP)                    // halves per operand per stage
#define GEMM_SMEM (2 * 2 * G_ST * 2)       // 40960 B

__global__ __launch_bounds__(256, 2) void gemm_h_kernel(
    const __half* __restrict__ A, const __half* __restrict__ WT,
    const float* __restrict__ bias, float* __restrict__ Cf,
    uint32_t* __restrict__ Ch, int N)
{
    extern __shared__ char smc[];
    const uint32_t aB[2] = { smem_u32(smc),            smem_u32(smc) + G_ST * 2 };
    const uint32_t bB[2] = { aB[1] + G_ST * 2,         aB[1] + 2 * G_ST * 2 };

    const int tid = threadIdx.x;
    const int wid = tid >> 5, lane = tid & 31;
    const int gID = lane >> 2, tg = lane & 3;
    const int rowl = lane & 7, grp = lane >> 3;
    const int bm = blockIdx.y * 128, bn = blockIdx.x * 128;
    const int wm = (wid & 3) * 32, wn = (wid >> 2) * 64;

    // ldmatrix lane offsets (halves)
    // A: r0=(m0-7,klo) r1=(m8-15,klo) r2=(m0-7,khi) r3=(m8-15,khi)
    const uint32_t aOff = (uint32_t)(((grp & 1) * 8 + rowl) * GP + (grp >> 1) * 8);
    // B: r0=(nlo,klo) r1=(nlo,khi) r2=(nhi,klo) r3=(nhi,khi)
    const uint32_t bOff = (uint32_t)(((grp >> 1) * 8 + rowl) * GP + (grp & 1) * 8);

    float acc[2][8][4];
    #pragma unroll
    for (int im = 0; im < 2; im++)
        #pragma unroll
        for (int n = 0; n < 8; n++)
            #pragma unroll
            for (int j = 0; j < 4; j++) acc[im][n][j] = 0.f;

    // prologue: chunks 0,1
    #pragma unroll
    for (int pi = 0; pi < 2; pi++) {
        const int k0 = pi * 32;
        #pragma unroll
        for (int j = 0; j < 2; j++) {
            const int idx = tid + j * 256;
            const int r = idx >> 2, c = idx & 3;
            CP_ASYNC16(aB[pi] + (uint32_t)(r * GP + c * 8) * 2u,
                       A + (size_t)(bm + r) * D + k0 + c * 8);
            CP_ASYNC16(bB[pi] + (uint32_t)(r * GP + c * 8) * 2u,
                       WT + (size_t)(bn + r) * D + k0 + c * 8);
        }
        CP_COMMIT();
    }

    for (int i = 0; i < 32; i++) {
        const int s = i & 1;
        if (i < 31) { CP_WAIT1(); } else { CP_WAIT0(); }
        __syncthreads();
        const uint32_t aS = aB[s], bS = bB[s];
        #pragma unroll
        for (int ks = 0; ks < 2; ks++) {
            uint32_t af[2][4];
            #pragma unroll
            for (int im = 0; im < 2; im++)
                LDSM_X4(af[im][0], af[im][1], af[im][2], af[im][3],
                        aS + (aOff + (uint32_t)((wm + im * 16) * GP + ks * 16)) * 2u);
            #pragma unroll
            for (int np = 0; np < 4; np++) {
                uint32_t b0, b1, b2, b3;
                LDSM_X4(b0, b1, b2, b3,
                        bS + (bOff + (uint32_t)((wn + np * 16) * GP + ks * 16)) * 2u);
                #pragma unroll
                for (int im = 0; im < 2; im++) {
                    mma_f16(acc[im][2*np][0], acc[im][2*np][1],
                            acc[im][2*np][2], acc[im][2*np][3],
                            af[im][0], af[im][1], af[im][2], af[im][3], b0, b1);
                    mma_f16(acc[im][2*np+1][0], acc[im][2*np+1][1],
                            acc[im][2*np+1][2], acc[im][2*np+1][3],
                            af[im][0], af[im][1], af[im][2], af[im][3], b2, b3);
                }
            }
        }
        __syncthreads();
        if (i + 2 < 32) {
            const int k0 = (i + 2) * 32;
            #pragma unroll
            for (int j = 0; j < 2; j++) {
                const int idx = tid + j * 256;
                const int r = idx >> 2, c = idx & 3;
                CP_ASYNC16(aB[s] + (uint32_t)(r * GP + c * 8) * 2u,
                           A + (size_t)(bm + r) * D + k0 + c * 8);
                CP_ASYNC16(bB[s] + (uint32_t)(r * GP + c * 8) * 2u,
                           WT + (size_t)(bn + r) * D + k0 + c * 8);
            }
            CP_COMMIT();
        }
    }

    // epilogue (acc: rows gID,gID+8; cols 2tg,2tg+1 within each n*8 group)
    #pragma unroll
    for (int im = 0; im < 2; im++) {
        const int r0 = bm + wm + im * 16 + gID;
        #pragma unroll
        for (int n = 0; n < 8; n++) {
            const int col = bn + wn + n * 8 + 2 * tg;
            float v0 = acc[im][n][0], v1 = acc[im][n][1];
            float v2 = acc[im][n][2], v3 = acc[im][n][3];
            if (bias) {
                const float b0 = bias[col], b1 = bias[col + 1];
                v0 += b0; v1 += b1; v2 += b0; v3 += b1;
            }
            if (Ch) {
                Ch[((size_t)r0 * N + col) >> 1]       = packh2(v0, v1);
                Ch[((size_t)(r0 + 8) * N + col) >> 1] = packh2(v2, v3);
            } else {
                *(float2*)&Cf[(size_t)r0 * N + col]       = make_float2(v0, v1);
                *(float2*)&Cf[(size_t)(r0 + 8) * N + col] = make_float2(v2, v3);
            }
        }
    }
}

// ---------------------------------------------------------------------------
// FP16 mma.sync flash attention (R11-good version, unchanged).
// ---------------------------------------------------------------------------
#define KPH 72
#define KV_TILE_B (64 * KPH * 2)            // 9216 B per K or V stage
#define ATTN_SMEM (2 * 2 * KV_TILE_B)       // 36864 B

__global__ __launch_bounds__(256, 2) void attn_kernel(
    const __half* __restrict__ qkv, uint32_t* __restrict__ ctxh)
{
    extern __shared__ char smc[];
    const uint32_t kB[2] = { smem_u32(smc),                 smem_u32(smc) + KV_TILE_B };
    const uint32_t vB[2] = { kB[0] + 2 * KV_TILE_B,         kB[1] + 2 * KV_TILE_B };

    const int tid = threadIdx.x;
    const int wid = tid >> 5, lane = tid & 31;
    const int gID = lane >> 2, tg = lane & 3;
    const int rowl = lane & 7, grp = lane >> 3;
    const int h = blockIdx.y, bb = blockIdx.z;
    const int qbase = blockIdx.x * 128 + wid * 16;

    const __half* qp = qkv + (size_t)(bb * S + qbase) * D3 + h * DH;
    const __half* kbase = qkv + (size_t)bb * S * D3 + INNER + h * DH;
    const __half* vbase = kbase + INNER;

    // Q fragments: raw fp16, u32 pair slots
    uint32_t qa[4][4];
    #pragma unroll
    for (int ks = 0; ks < 4; ks++) {
        qa[ks][0] = *(const uint32_t*)(qp + (size_t)gID * D3 + 16 * ks + 2 * tg);
        qa[ks][1] = *(const uint32_t*)(qp + (size_t)(gID + 8) * D3 + 16 * ks + 2 * tg);
        qa[ks][2] = *(const uint32_t*)(qp + (size_t)gID * D3 + 16 * ks + 2 * tg + 8);
        qa[ks][3] = *(const uint32_t*)(qp + (size_t)(gID + 8) * D3 + 16 * ks + 2 * tg + 8);
    }

    const uint32_t k_lane_off = (uint32_t)((((grp >> 1) * 8 + rowl) * KPH + (grp & 1) * 8) * 2);
    const uint32_t v_lane_off = (uint32_t)((((grp & 1) * 8 + rowl) * KPH + (grp >> 1) * 8) * 2);

    float o[8][4];
    #pragma unroll
    for (int n = 0; n < 8; n++)
        #pragma unroll
        for (int j = 0; j < 4; j++) o[n][j] = 0.f;
    float m0 = -1e30f, m1 = -1e30f, l0 = 0.f, l1 = 0.f;
    const float CS = QSCALE_LOG2E;

    // prologue: tiles 0,1
    #pragma unroll
    for (int pi = 0; pi < 2; pi++) {
        const int r0 = pi * 64;
        #pragma unroll
        for (int j = 0; j < 2; j++) {
            const int idx = tid + j * 256;
            const int r = idx >> 3, c = idx & 7;
            CP_ASYNC16(kB[pi] + (uint32_t)(r * KPH + c * 8) * 2u,
                       kbase + (size_t)(r0 + r) * D3 + c * 8);
            CP_ASYNC16(vB[pi] + (uint32_t)(r * KPH + c * 8) * 2u,
                       vbase + (size_t)(r0 + r) * D3 + c * 8);
        }
        CP_COMMIT();
    }

    for (int i = 0; i < 32; i++) {
        const int s = i & 1;
        if (i < 31) { CP_WAIT1(); } else { CP_WAIT0(); }
        __syncthreads();

        // ---- S = Q @ K^T ----
        float sa[8][4];
        #pragma unroll
        for (int n = 0; n < 8; n++)
            #pragma unroll
            for (int j = 0; j < 4; j++) sa[n][j] = 0.f;
        #pragma unroll
        for (int ks = 0; ks < 4; ks++) {
            #pragma unroll
            for (int np = 0; np < 4; np++) {
                uint32_t r0, r1, r2, r3;
                LDSM_X4(r0, r1, r2, r3,
                        kB[s] + k_lane_off + (uint32_t)((np * 16 * KPH + ks * 16) * 2));
                mma_f16(sa[2*np][0], sa[2*np][1], sa[2*np][2], sa[2*np][3],
                        qa[ks][0], qa[ks][1], qa[ks][2], qa[ks][3], r0, r1);
                mma_f16(sa[2*np+1][0], sa[2*np+1][1], sa[2*np+1][2], sa[2*np+1][3],
                        qa[ks][0], qa[ks][1], qa[ks][2], qa[ks][3], r2, r3);
            }
        }

        // ---- online softmax (base 2, scale via fma; P packed to half2) ----
        float rmax0 = sa[0][0], rmax1 = sa[0][2];
        #pragma unroll
        for (int n = 0; n < 8; n++) {
            rmax0 = fmaxf(rmax0, fmaxf(sa[n][0], sa[n][1]));
            rmax1 = fmaxf(rmax1, fmaxf(sa[n][2], sa[n][3]));
        }
        rmax0 = fmaxf(rmax0, __shfl_xor_sync(0xffffffffu, rmax0, 1));
        rmax0 = fmaxf(rmax0, __shfl_xor_sync(0xffffffffu, rmax0, 2));
        rmax1 = fmaxf(rmax1, __shfl_xor_sync(0xffffffffu, rmax1, 1));
        rmax1 = fmaxf(rmax1, __shfl_xor_sync(0xffffffffu, rmax1, 2));
        const float nm0 = fmaxf(m0, rmax0 * CS), nm1 = fmaxf(m1, rmax1 * CS);
        const float c0 = ex2f(m0 - nm0), c1 = ex2f(m1 - nm1);
        m0 = nm0; m1 = nm1;
        float s0 = 0.f, s1 = 0.f;
        uint32_t p01[8], p23[8];
        #pragma unroll
        for (int n = 0; n < 8; n++) {
            const float p0 = ex2f(fmaf(sa[n][0], CS, -m0));
            const float p1 = ex2f(fmaf(sa[n][1], CS, -m0));
            const float p2 = ex2f(fmaf(sa[n][2], CS, -m1));
            const float p3 = ex2f(fmaf(sa[n][3], CS, -m1));
            s0 += p0 + p1; s1 += p2 + p3;
            p01[n] = packh2(p0, p1);
            p23[n] = packh2(p2, p3);
            o[n][0] *= c0; o[n][1] *= c0; o[n][2] *= c1; o[n][3] *= c1;
        }
        s0 += __shfl_xor_sync(0xffffffffu, s0, 1);
        s0 += __shfl_xor_sync(0xffffffffu, s0, 2);
        s1 += __shfl_xor_sync(0xffffffffu, s1, 1);
        s1 += __shfl_xor_sync(0xffffffffu, s1, 2);
        l0 = l0 * c0 + s0;
        l1 = l1 * c1 + s1;

        // ---- O += P @ V (ldmatrix.trans V fragments) ----
        #pragma unroll
        for (int kc = 0; kc < 4; kc++) {
            const uint32_t a0 = p01[2*kc], a1 = p23[2*kc];
            const uint32_t a2 = p01[2*kc+1], a3 = p23[2*kc+1];
            #pragma unroll
            for (int cp = 0; cp < 4; cp++) {
                uint32_t r0, r1, r2, r3;
                LDSM_X4_T(r0, r1, r2, r3,
                          vB[s] + v_lane_off + (uint32_t)((kc * 16 * KPH + cp * 16) * 2));
                mma_f16(o[2*cp][0], o[2*cp][1], o[2*cp][2], o[2*cp][3],
                        a0, a1, a2, a3, r0, r1);
                mma_f16(o[2*cp+1][0], o[2*cp+1][1], o[2*cp+1][2], o[2*cp+1][3],
                        a0, a1, a2, a3, r2, r3);
            }
        }
        __syncthreads();

        if (i + 2 < 32) {
            const int r0 = (i + 2) * 64;
            #pragma unroll
            for (int j = 0; j < 2; j++) {
                const int idx = tid + j * 256;
                const int r = idx >> 3, c = idx & 7;
                CP_ASYNC16(kB[s] + (uint32_t)(r * KPH + c * 8) * 2u,
                           kbase + (size_t)(r0 + r) * D3 + c * 8);
                CP_ASYNC16(vB[s] + (uint32_t)(r * KPH + c * 8) * 2u,
                           vbase + (size_t)(r0 + r) * D3 + c * 8);
            }
            CP_COMMIT();
        }
    }

    // epilogue: normalize, write fp16 half2 pairs
    const float inv0 = 1.f / l0, inv1 = 1.f / l1;
    const size_t grow = (size_t)(bb * S + qbase + gID);
    #pragma unroll
    for (int n = 0; n < 8; n++) {
        const int col = h * DH + n * 8 + 2 * tg;
        ctxh[(grow * INNER + col) >> 1] =
            packh2(o[n][0] * inv0, o[n][1] * inv0);
        ctxh[((grow + 8) * INNER + col) >> 1] =
            packh2(o[n][2] * inv1, o[n][3] * inv1);
    }
}

// ---------------------------------------------------------------------------
extern "C" void kernel_launch(void* const* d_in, const int* in_sizes, int n_in,
                              void* d_out, int out_size)
{
    const float* x        = (const float*)d_in[0];
    const float* ln_gamma = (const float*)d_in[1];
    const float* ln_beta  = (const float*)d_in[2];
    const float* w_qkv    = (const float*)d_in[3];
    const float* w_out    = (const float*)d_in[4];
    const float* b_out    = (const float*)d_in[5];
    float* out = (float*)d_out;

    void* sp = nullptr;
    cudaGetSymbolAddress(&sp, g_scratch);
    float* base = (float*)sp;
    uint32_t* xnh  = (uint32_t*)base;                        // ROWS*D halves
    uint32_t* qkvh = xnh + (size_t)ROWS * D / 2;             // ROWS*D3 halves
    uint32_t* ctxh = qkvh + (size_t)ROWS * D3 / 2;           // ROWS*D halves
    __half*   wqT  = (__half*)(ctxh + (size_t)ROWS * D / 2); // [D3][D] halves
    __half*   woT  = wqT + (size_t)D3 * D;                   // [D][D] halves

    cudaFuncSetAttribute(gemm_h_kernel, cudaFuncAttributeMaxDynamicSharedMemorySize, GEMM_SMEM);
    cudaFuncSetAttribute(attn_kernel, cudaFuncAttributeMaxDynamicSharedMemorySize, ATTN_SMEM);

    // transpose + pack weights to fp16 [N][K]
    pack_wT_kernel<<<dim3(D3 / 32, D / 32), dim3(32, 8)>>>(w_qkv, wqT, D3);
    pack_wT_kernel<<<dim3(D / 32, D / 32), dim3(32, 8)>>>(w_out, woT, D);

    // 1. LayerNorm (fp16 output)
    ln_kernel<<<ROWS, 256>>>(x, ln_gamma, ln_beta, xnh);

    // 2. QKV projection (fp16 tensor cores + ldmatrix, fp16 output)
    gemm_h_kernel<<<dim3(D3 / 128, ROWS / 128), 256, GEMM_SMEM>>>(
        (const __half*)xnh, wqT, nullptr, nullptr, qkvh, D3);

    // 3. Flash attention (fp16 tensor cores + ldmatrix, fp16 ctx output)
    attn_kernel<<<dim3(S / 128, HEADS, B), 256, ATTN_SMEM>>>(
        (const __half*)qkvh, ctxh);

    // 4. Output projection + bias (fp16 tensor cores + ldmatrix, fp32 out)
    gemm_h_kernel<<<dim3(D / 128, ROWS / 128), 256, GEMM_SMEM>>>(
        (const __half*)ctxh, woT, b_out, out, nullptr, D);
}